// round 12
// baseline (speedup 1.0000x reference)
#include <cuda_runtime.h>

// PlanarQuantMSE — register-band quantizer (zero LDS on the hot path).
// Per-row normalize, rotate pairs, quantize to nearest of 16 SORTED centroids,
// inverse-rotate, rescale. Output: [x_hat | indices-as-float] concatenated.
//
// Data insight: unit-row components have sigma = 1/64, so rotated values r lie
// in (m5, m9] (central midpoint band) for essentially every element. There:
//   idx = 6 + (r>m6) + (r>m7) + (r>m8)      -- 3 register compares
//   q   = 3-way select among c6..c9          -- registers
// identical boundary semantics to the verified LUT kernels (r > m_j, strict).
// Out-of-band lanes -> __any_sync-gated slow block: exact 15-compare chain
// over mid_sh (always correct, ~never taken).

#define ROWS 4096
#define DIM  4096
#define TPB  256
#define VPT  4        // float4s per thread (TPB*4*VPT == DIM)

__global__ __launch_bounds__(TPB, 5)
void pq_kernel(const float* __restrict__ x,
               const float* __restrict__ cent,
               const float* __restrict__ rot2,
               float* __restrict__ xhat,
               float* __restrict__ idxout)
{
    __shared__ float mid_sh[16];
    __shared__ float c_sh[16];
    __shared__ float red[TPB / 32];
    __shared__ float norm_sh;

    const int row = blockIdx.x;
    const int t   = threadIdx.x;

    // ---- issue x loads first so DRAM streams while we do setup ----
    const float4* xr = (const float4*)(x + (size_t)row * DIM);
    float4 v[VPT];
#pragma unroll
    for (int k = 0; k < VPT; k++) v[k] = xr[t + k * TPB];

    // ---- warp-0 setup: centroids + midpoints (same rounding as verified) ----
    if (t < 16) {
        float cv = __ldg(&cent[t]);
        c_sh[t] = cv;
        float cn = __shfl_down_sync(0x0000ffffu, cv, 1);
        float mm = 0.5f * (cv + cn);
        if (t < 15) mid_sh[t] = mm;
        else        mid_sh[15] = 3.0e38f;
    }

    // ---- row sum of squares ----
    float ss = 0.0f;
#pragma unroll
    for (int k = 0; k < VPT; k++)
        ss += v[k].x * v[k].x + v[k].y * v[k].y
            + v[k].z * v[k].z + v[k].w * v[k].w;
#pragma unroll
    for (int o = 16; o > 0; o >>= 1)
        ss += __shfl_xor_sync(0xffffffffu, ss, o);
    if ((t & 31) == 0) red[t >> 5] = ss;
    __syncthreads();                                   // barrier A

    if (t < (TPB / 32)) {
        float s2 = red[t];
#pragma unroll
        for (int o = (TPB / 64); o > 0; o >>= 1)
            s2 += __shfl_xor_sync((1u << (TPB / 32)) - 1u, s2, o);
        if (t == 0) norm_sh = fmaxf(sqrtf(s2), 1e-8f);
    }
    __syncthreads();                                   // barrier B

    const float norm = norm_sh;
    const float inv  = 1.0f / norm;

    // band constants -> registers (broadcast LDS, once per thread)
    const float m5 = mid_sh[5], m6 = mid_sh[6], m7 = mid_sh[7];
    const float m8 = mid_sh[8], m9 = mid_sh[9];
    const float c6 = c_sh[6], c7 = c_sh[7], c8 = c_sh[8], c9 = c_sh[9];

    const float4* rr = (const float4*)rot2;            // (c,s,c,s) per float4
    float4* xo = (float4*)(xhat  + (size_t)row * DIM);
    float4* io = (float4*)(idxout + (size_t)row * DIM);

#pragma unroll
    for (int k = 0; k < VPT; k++) {
        const int j = t + k * TPB;
        const float4 rs = __ldg(&rr[j]);

        const float v0 = v[k].x * inv, v1 = v[k].y * inv;
        const float v2 = v[k].z * inv, v3 = v[k].w * inv;

        float r[4];
        r[0] = rs.x * v0 - rs.y * v1;
        r[1] = rs.y * v0 + rs.x * v1;
        r[2] = rs.z * v2 - rs.w * v3;
        r[3] = rs.w * v2 + rs.z * v3;

        float q[4], f[4];
        bool  ob = false;
#pragma unroll
        for (int e = 0; e < 4; e++) {
            const bool s6 = r[e] > m6;
            const bool s7 = r[e] > m7;
            const bool s8 = r[e] > m8;
            const int idx = 6 + (s6 ? 1 : 0) + (s7 ? 1 : 0) + (s8 ? 1 : 0);
            q[e] = s7 ? (s8 ? c9 : c8) : (s6 ? c7 : c6);
            f[e] = (float)idx;
            // out-of-band guard: idx formula valid only for m5 < r <= m9
            ob = ob || (r[e] > m9) || !(r[e] > m5);
        }
        if (__any_sync(0xffffffffu, ob)) {             // ~never taken
#pragma unroll
            for (int e = 0; e < 4; e++) {
                int idx = 0;
#pragma unroll
                for (int jj = 0; jj < 15; jj++) idx += (r[e] > mid_sh[jj]) ? 1 : 0;
                q[e] = c_sh[idx];
                f[e] = (float)idx;
            }
        }

        float4 out;
        out.x = (rs.x * q[0] + rs.y * q[1]) * norm;
        out.y = (rs.x * q[1] - rs.y * q[0]) * norm;
        out.z = (rs.z * q[2] + rs.w * q[3]) * norm;
        out.w = (rs.z * q[3] - rs.w * q[2]) * norm;
        xo[j] = out;

        float4 fo;
        fo.x = f[0]; fo.y = f[1]; fo.z = f[2]; fo.w = f[3];
        io[j] = fo;
    }
}

extern "C" void kernel_launch(void* const* d_in, const int* in_sizes, int n_in,
                              void* d_out, int out_size) {
    const float* x = nullptr;
    const float* cent = nullptr;
    const float* rot2 = nullptr;
    for (int i = 0; i < n_in; i++) {
        if (in_sizes[i] == ROWS * DIM) x    = (const float*)d_in[i];
        else if (in_sizes[i] == 16)    cent = (const float*)d_in[i];
        else if (in_sizes[i] == 4096)  rot2 = (const float*)d_in[i];
    }

    float* xhat = (float*)d_out;
    float* idxf = xhat + (long long)ROWS * DIM;

    pq_kernel<<<ROWS, TPB>>>(x, cent, rot2, xhat, idxf);
}

// round 13
// speedup vs baseline: 1.2976x; 1.2976x over previous
#include <cuda_runtime.h>

// PlanarQuantMSE — cp.async double-buffered row pipeline.
// Grid 1024, each CTA processes rows {bid, bid+1024, bid+2048, bid+3072}.
// x is staged gmem->smem via cp.async.cg (LDGSTS: no register footprint),
// double-buffered so row i+1/i+2 reads stream while row i computes/stores.
// Each thread touches only its own smem slots -> buffer reuse is thread-local
// (no extra barriers). One barrier per row (red[2] double buffer).
// rot2 loaded once per CTA into registers (reused all 4 rows).
// Quantizer: R10 byte-LUT, exact boundary (lut[cell]->L; r>mid_sh[L]; c_sh[idx]).
// Output: [x_hat | indices-as-float] concatenated.

#define ROWS 4096
#define DIM  4096
#define TPB  256
#define VPT  4        // float4s per thread per row (TPB*4*VPT == DIM)
#define GRID 1024
#define NROW 4        // rows per CTA  (GRID*NROW == ROWS)
#define NCELL 1024
#define SCALEF 455.0f
// magic = 2^23*1.5 + 512 ; cell = bits(fma(v,S,magic)) - 0x4B400000 = round(v*S)+512
// |r| <= 1+3e-7 => cell in [57, 968]: no clamp needed.
#define MAGICF 12583424.0f
#define BITBASE 0x4B400000

__device__ __forceinline__ void cp_async16(unsigned dst, const void* src) {
    asm volatile("cp.async.cg.shared.global [%0], [%1], 16;"
                 :: "r"(dst), "l"(src) : "memory");
}

__global__ __launch_bounds__(TPB, 6)
void pq_kernel(const float* __restrict__ x,
               const float* __restrict__ cent,
               const float* __restrict__ rot2,
               float* __restrict__ xhat,
               float* __restrict__ idxout)
{
    __shared__ float xbuf[2][DIM];            // 32 KB ring
    __shared__ unsigned char lut_sh[NCELL];
    __shared__ float  mid_sh[16];
    __shared__ float  c_sh[16];
    __shared__ int    tc_sh[15];
    __shared__ float  red[2][TPB / 32];
    __shared__ int    flag_sh;

    const int bid = blockIdx.x;
    const int t   = threadIdx.x;
    const int w   = t >> 5;

    // ---- prologue: async-load rows 0 and 1 (DRAM starts streaming now) ----
#pragma unroll
    for (int b = 0; b < 2; b++) {
        const float* src = x + (size_t)(bid + b * GRID) * DIM;
        unsigned dst = (unsigned)__cvta_generic_to_shared(&xbuf[b][0]);
#pragma unroll
        for (int k = 0; k < VPT; k++) {
            const int e = t + k * TPB;                 // float4 index
            cp_async16(dst + e * 16, src + e * 4);
        }
        asm volatile("cp.async.commit_group;" ::: "memory");
    }

    // ---- warp-0 table setup ----
    if (t < 16) {
        float cv = __ldg(&cent[t]);
        c_sh[t] = cv;
        float cn = __shfl_down_sync(0x0000ffffu, cv, 1);
        float mm = 0.5f * (cv + cn);
        int cell = __float_as_int(fmaf(mm, SCALEF, MAGICF)) - BITBASE;
        if (t < 15) { mid_sh[t] = mm; tc_sh[t] = cell; }
        else        { mid_sh[15] = 3.0e38f; }
        int celln = __shfl_down_sync(0x0000ffffu, cell, 1);
        unsigned dup = __ballot_sync(0x0000ffffu, (t < 14) && (cell == celln));
        if (t == 0) flag_sh = (dup != 0u) ? 1 : 0;
    }

    // ---- rot2 into registers, reused for all rows ----
    const float4* rr = (const float4*)rot2;
    float4 rs[VPT];
#pragma unroll
    for (int k = 0; k < VPT; k++) rs[k] = __ldg(&rr[t + k * TPB]);

    __syncthreads();                                   // tc_sh visible

    // ---- byte-LUT build: 4 cells/thread, one packed STS.32 ----
    {
        const int base = t * 4;
        int L0 = 0, L1 = 0, L2 = 0, L3 = 0;
#pragma unroll
        for (int j = 0; j < 15; j++) {
            int cj = tc_sh[j];
            L0 += (cj < base)     ? 1 : 0;
            L1 += (cj < base + 1) ? 1 : 0;
            L2 += (cj < base + 2) ? 1 : 0;
            L3 += (cj < base + 3) ? 1 : 0;
        }
        ((unsigned int*)lut_sh)[t] =
            (unsigned)L0 | ((unsigned)L1 << 8) | ((unsigned)L2 << 16) | ((unsigned)L3 << 24);
    }
    __syncthreads();                                   // lut_sh visible
    const int flag = flag_sh;

    // ---- pipelined row loop ----
#pragma unroll
    for (int i = 0; i < NROW; i++) {
        // own copies for buffer i&1 complete (thread-local FIFO semantics)
        if (i < NROW - 1) asm volatile("cp.async.wait_group 1;" ::: "memory");
        else              asm volatile("cp.async.wait_group 0;" ::: "memory");

        const float4* xb = (const float4*)&xbuf[i & 1][0];

        // sum of squares from smem
        float ss = 0.0f;
#pragma unroll
        for (int k = 0; k < VPT; k++) {
            float4 xv = xb[t + k * TPB];
            ss += xv.x * xv.x + xv.y * xv.y + xv.z * xv.z + xv.w * xv.w;
        }
#pragma unroll
        for (int o = 16; o > 0; o >>= 1)
            ss += __shfl_xor_sync(0xffffffffu, ss, o);
        if ((t & 31) == 0) red[i & 1][w] = ss;
        __syncthreads();                               // one barrier per row

        float s2 = 0.0f;
#pragma unroll
        for (int p = 0; p < TPB / 32; p++) s2 += red[i & 1][p];
        const float norm = fmaxf(sqrtf(s2), 1e-8f);
        const float inv  = 1.0f / norm;

        const int row = bid + i * GRID;
        float4* xo = (float4*)(xhat   + (size_t)row * DIM);
        float4* io = (float4*)(idxout + (size_t)row * DIM);

#pragma unroll
        for (int k = 0; k < VPT; k++) {
            const int j = t + k * TPB;
            const float4 xv = xb[j];

            const float v0 = xv.x * inv, v1 = xv.y * inv;
            const float v2 = xv.z * inv, v3 = xv.w * inv;

            float r[4];
            r[0] = rs[k].x * v0 - rs[k].y * v1;
            r[1] = rs[k].y * v0 + rs[k].x * v1;
            r[2] = rs[k].z * v2 - rs[k].w * v3;
            r[3] = rs[k].w * v2 + rs[k].z * v3;

            float q[4], f[4];
            if (!flag) {
#pragma unroll
                for (int e = 0; e < 4; e++) {
                    int cell = __float_as_int(fmaf(r[e], SCALEF, MAGICF)) - BITBASE;
                    int L    = (int)lut_sh[cell];
                    int idx  = L + ((r[e] > mid_sh[L]) ? 1 : 0);
                    q[e] = c_sh[idx];
                    f[e] = (float)idx;
                }
            } else {
#pragma unroll
                for (int e = 0; e < 4; e++) {
                    int idx = 0;
#pragma unroll
                    for (int jj = 0; jj < 15; jj++) idx += (r[e] > mid_sh[jj]) ? 1 : 0;
                    q[e] = c_sh[idx];
                    f[e] = (float)idx;
                }
            }

            float4 out;
            out.x = (rs[k].x * q[0] + rs[k].y * q[1]) * norm;
            out.y = (rs[k].x * q[1] - rs[k].y * q[0]) * norm;
            out.z = (rs[k].z * q[2] + rs[k].w * q[3]) * norm;
            out.w = (rs[k].z * q[3] - rs[k].w * q[2]) * norm;
            xo[j] = out;

            float4 fo;
            fo.x = f[0]; fo.y = f[1]; fo.z = f[2]; fo.w = f[3];
            io[j] = fo;
        }

        // refill this buffer with row i+2 (thread-local: our reads are done)
        if (i + 2 < NROW) {
            const float* src = x + (size_t)(bid + (i + 2) * GRID) * DIM;
            unsigned dst = (unsigned)__cvta_generic_to_shared(&xbuf[i & 1][0]);
#pragma unroll
            for (int k = 0; k < VPT; k++) {
                const int e = t + k * TPB;
                cp_async16(dst + e * 16, src + e * 4);
            }
            asm volatile("cp.async.commit_group;" ::: "memory");
        }
    }
}

extern "C" void kernel_launch(void* const* d_in, const int* in_sizes, int n_in,
                              void* d_out, int out_size) {
    const float* x = nullptr;
    const float* cent = nullptr;
    const float* rot2 = nullptr;
    for (int i = 0; i < n_in; i++) {
        if (in_sizes[i] == ROWS * DIM) x    = (const float*)d_in[i];
        else if (in_sizes[i] == 16)    cent = (const float*)d_in[i];
        else if (in_sizes[i] == 4096)  rot2 = (const float*)d_in[i];
    }

    float* xhat = (float*)d_out;
    float* idxf = xhat + (long long)ROWS * DIM;

    pq_kernel<<<GRID, TPB>>>(x, cent, rot2, xhat, idxf);
}

// round 14
// speedup vs baseline: 1.3235x; 1.0199x over previous
#include <cuda_runtime.h>

// PlanarQuantMSE — R10 structure; single change: x loads use __ldcs.
// Rationale: output buffers are re-written every graph replay, so dirty lines
// that stay resident in the 126MB L2 across replays never cost DRAM writeback.
// Evict-first reads keep the 64MB read stream from displacing the write set;
// DEFAULT stores keep writes resident. (R8 proved __stcs stores hurt; R10
// proved default reads leave perf on the table.)
// Quantizer: byte-LUT, exact boundary (lut[cell]->L; r>mid_sh[L]; c_sh[idx]).
// Output: [x_hat | indices-as-float] concatenated.

#define ROWS 4096
#define DIM  4096
#define TPB  256
#define VPT  4        // float4s per thread (TPB*4*VPT == DIM)
#define NCELL 1024
#define SCALEF 455.0f
// magic = 2^23*1.5 + 512 ; cell = bits(fma(v,S,magic)) - 0x4B400000 = round(v*S)+512
// |r| <= 1+3e-7 (rotated unit-subvector pair) => cell in [57, 968]: no clamp.
#define MAGICF 12583424.0f
#define BITBASE 0x4B400000

__global__ __launch_bounds__(TPB, 6)
void pq_kernel(const float* __restrict__ x,
               const float* __restrict__ cent,
               const float* __restrict__ rot2,
               float* __restrict__ xhat,
               float* __restrict__ idxout)
{
    __shared__ unsigned char lut_sh[NCELL];
    __shared__ float  mid_sh[16];
    __shared__ float  c_sh[16];
    __shared__ int    tc_sh[15];
    __shared__ float  red[TPB / 32];
    __shared__ float  norm_sh;
    __shared__ int    flag_sh;

    const int row = blockIdx.x;
    const int t   = threadIdx.x;

    // ---- issue x loads first; evict-first so they don't displace the
    //      L2-resident output write set ----
    const float4* xr = (const float4*)(x + (size_t)row * DIM);
    float4 v[VPT];
#pragma unroll
    for (int k = 0; k < VPT; k++) v[k] = __ldcs(&xr[t + k * TPB]);

    // ---- warp-0 setup: centroids, midpoints, cell ids, dup flag ----
    if (t < 16) {
        float cv = __ldg(&cent[t]);
        c_sh[t] = cv;
        float cn = __shfl_down_sync(0x0000ffffu, cv, 1);
        float mm = 0.5f * (cv + cn);
        int cell = __float_as_int(fmaf(mm, SCALEF, MAGICF)) - BITBASE;
        if (t < 15) { mid_sh[t] = mm; tc_sh[t] = cell; }
        else        { mid_sh[15] = 3.0e38f; }
        int celln = __shfl_down_sync(0x0000ffffu, cell, 1);
        unsigned dup = __ballot_sync(0x0000ffffu, (t < 14) && (cell == celln));
        if (t == 0) flag_sh = (dup != 0u) ? 1 : 0;
    }

    // ---- row sum of squares ----
    float ss = 0.0f;
#pragma unroll
    for (int k = 0; k < VPT; k++)
        ss += v[k].x * v[k].x + v[k].y * v[k].y
            + v[k].z * v[k].z + v[k].w * v[k].w;
#pragma unroll
    for (int o = 16; o > 0; o >>= 1)
        ss += __shfl_xor_sync(0xffffffffu, ss, o);
    if ((t & 31) == 0) red[t >> 5] = ss;
    __syncthreads();                                   // barrier A

    // ---- byte-LUT build: 4 cells/thread, one packed STS.32 ----
    {
        const int base = t * 4;
        int L0 = 0, L1 = 0, L2 = 0, L3 = 0;
#pragma unroll
        for (int j = 0; j < 15; j++) {
            int cj = tc_sh[j];
            L0 += (cj < base)     ? 1 : 0;
            L1 += (cj < base + 1) ? 1 : 0;
            L2 += (cj < base + 2) ? 1 : 0;
            L3 += (cj < base + 3) ? 1 : 0;
        }
        ((unsigned int*)lut_sh)[t] =
            (unsigned)L0 | ((unsigned)L1 << 8) | ((unsigned)L2 << 16) | ((unsigned)L3 << 24);
    }

    if (t < (TPB / 32)) {
        float s2 = red[t];
#pragma unroll
        for (int o = (TPB / 64); o > 0; o >>= 1)
            s2 += __shfl_xor_sync((1u << (TPB / 32)) - 1u, s2, o);
        if (t == 0) norm_sh = fmaxf(sqrtf(s2), 1e-8f);
    }
    __syncthreads();                                   // barrier B

    const float norm = norm_sh;
    const float inv  = 1.0f / norm;
    const int   flag = flag_sh;

    const float4* rr = (const float4*)rot2;            // (c,s,c,s) per float4
    float4* xo = (float4*)(xhat  + (size_t)row * DIM);
    float4* io = (float4*)(idxout + (size_t)row * DIM);

#pragma unroll
    for (int k = 0; k < VPT; k++) {
        const int j = t + k * TPB;
        const float4 rs = __ldg(&rr[j]);

        const float v0 = v[k].x * inv, v1 = v[k].y * inv;
        const float v2 = v[k].z * inv, v3 = v[k].w * inv;

        float r[4];
        r[0] = rs.x * v0 - rs.y * v1;
        r[1] = rs.y * v0 + rs.x * v1;
        r[2] = rs.z * v2 - rs.w * v3;
        r[3] = rs.w * v2 + rs.z * v3;

        float q[4], f[4];
        if (!flag) {
#pragma unroll
            for (int e = 0; e < 4; e++) {
                int cell = __float_as_int(fmaf(r[e], SCALEF, MAGICF)) - BITBASE;
                int L    = (int)lut_sh[cell];                 // narrow byte LDS
                int idx  = L + ((r[e] > mid_sh[L]) ? 1 : 0);  // bcast + exact cmp
                q[e] = c_sh[idx];                             // bcast
                f[e] = (float)idx;
            }
        } else {
#pragma unroll
            for (int e = 0; e < 4; e++) {
                int idx = 0;
#pragma unroll
                for (int jj = 0; jj < 15; jj++) idx += (r[e] > mid_sh[jj]) ? 1 : 0;
                q[e] = c_sh[idx];
                f[e] = (float)idx;
            }
        }

        float4 out;
        out.x = (rs.x * q[0] + rs.y * q[1]) * norm;
        out.y = (rs.x * q[1] - rs.y * q[0]) * norm;
        out.z = (rs.z * q[2] + rs.w * q[3]) * norm;
        out.w = (rs.z * q[3] - rs.w * q[2]) * norm;
        xo[j] = out;                                   // DEFAULT: stay L2-resident

        float4 fo;
        fo.x = f[0]; fo.y = f[1]; fo.z = f[2]; fo.w = f[3];
        io[j] = fo;                                    // DEFAULT: stay L2-resident
    }
}

extern "C" void kernel_launch(void* const* d_in, const int* in_sizes, int n_in,
                              void* d_out, int out_size) {
    const float* x = nullptr;
    const float* cent = nullptr;
    const float* rot2 = nullptr;
    for (int i = 0; i < n_in; i++) {
        if (in_sizes[i] == ROWS * DIM) x    = (const float*)d_in[i];
        else if (in_sizes[i] == 16)    cent = (const float*)d_in[i];
        else if (in_sizes[i] == 4096)  rot2 = (const float*)d_in[i];
    }

    float* xhat = (float*)d_out;
    float* idxf = xhat + (long long)ROWS * DIM;

    pq_kernel<<<ROWS, TPB>>>(x, cent, rot2, xhat, idxf);
}